// round 3
// baseline (speedup 1.0000x reference)
#include <cuda_runtime.h>
#include <cuda_bf16.h>
#include <cstdint>

#define Bv 4
#define Nv 4096
#define Cv 192
#define CIN 195
#define KCH 208             // padded input channels (13 * 16)
#define NSTEP 13
#define WSTRIDE 432         // row stride bytes (27*16B; 108 words = 12 mod 32 -> conflict-free)
#define WROWS 192
#define HROWS 128
#define W_BYTES (WROWS * WSTRIDE)     // 82944
#define H_BYTES (HROWS * WSTRIDE)     // 55296
#define SM_WH 0
#define SM_WL W_BYTES
#define SM_H (2 * W_BYTES)
#define SM_STAGE (2 * W_BYTES + H_BYTES)
#define SMEM_TOTAL (SM_STAGE + 4 * Cv * 4 + 256)   // 224512 <= 232448
#define NTILES 4096
#define GRID_MAIN 152
#define TPB 256

// ---------------- device scratch (no allocation allowed) ----------------
__device__ float g_xt[Bv * Nv * Cv];              // (x+1), [b][n][c]
__device__ float2 g_trig[Bv * Nv * 3 * 32];       // (sin, cos)(50*p*m_f)
__device__ unsigned short g_wh[WROWS * (WSTRIDE / 2)];
__device__ unsigned short g_wl[WROWS * (WSTRIDE / 2)];
__device__ float g_bias[Cv];

// ---------------- PTX helpers ----------------
__device__ __forceinline__ unsigned smem_u32(const void* p) {
    unsigned a;
    asm("{ .reg .u64 t; cvta.to.shared.u64 t, %1; cvt.u32.u64 %0, t; }" : "=r"(a) : "l"(p));
    return a;
}
#define LDSM4(r, a) \
    asm volatile("ldmatrix.sync.aligned.m8n8.x4.shared.b16 {%0,%1,%2,%3}, [%4];" \
        : "=r"((r)[0]), "=r"((r)[1]), "=r"((r)[2]), "=r"((r)[3]) : "r"(a))
#define MMA(d, a, b0, b1) \
    asm volatile("mma.sync.aligned.m16n8k16.row.col.f32.bf16.bf16.f32 " \
        "{%0,%1,%2,%3},{%4,%5,%6,%7},{%8,%9},{%0,%1,%2,%3};" \
        : "+f"((d)[0]), "+f"((d)[1]), "+f"((d)[2]), "+f"((d)[3]) \
        : "r"((a)[0]), "r"((a)[1]), "r"((a)[2]), "r"((a)[3]), "r"(b0), "r"(b1))

// ---------------------------------------------------------------------------
// Kernel 1: transpose x [B,C,N] -> xt [B,N,C], fused +1
// ---------------------------------------------------------------------------
__global__ void transpose_add1(const float* __restrict__ x) {
    __shared__ float tile[32][33];
    int n0 = blockIdx.x * 32, c0 = blockIdx.y * 32, b = blockIdx.z;
    int tx = threadIdx.x, ty = threadIdx.y;
#pragma unroll
    for (int i = 0; i < 4; i++)
        tile[ty + i * 8][tx] = x[((size_t)b * Cv + c0 + ty + i * 8) * Nv + n0 + tx];
    __syncthreads();
#pragma unroll
    for (int i = 0; i < 4; i++)
        g_xt[((size_t)b * Nv + n0 + ty + i * 8) * Cv + c0 + tx] = tile[tx][ty + i * 8] + 1.0f;
}

// ---------------------------------------------------------------------------
// Kernel 2: per-point trig table  (sin, cos)(50 * p[b][n][d] * 500^(-f/32))
// ---------------------------------------------------------------------------
__global__ void trig_pre(const float* __restrict__ p) {
    int t = blockIdx.x * blockDim.x + threadIdx.x;
    if (t >= Bv * Nv * 96) return;
    int f = t & 31;
    int pd = t >> 5;                 // (b*Nv+n)*3 + d
    float m = (float)exp2(-(double)f * (8.9657842846620870436 / 32.0));
    float arg = 50.0f * p[pd] * m;
    float s, c;
    sincosf(arg, &s, &c);            // full-accuracy libdevice path (prologue only)
    g_trig[t] = make_float2(s, c);
}

// ---------------------------------------------------------------------------
// Kernel 3: fold BN into W, bf16 hi/lo split, [o][c] rows of 432B; bias.
//           channel order: 0..191 pe (old c+3), 192..194 dp (old 0..2), pad 0
// ---------------------------------------------------------------------------
__global__ void prep_w(const float* __restrict__ W, const float* __restrict__ gamma,
                       const float* __restrict__ beta, const float* __restrict__ rmean,
                       const float* __restrict__ rvar) {
    int t = blockIdx.x * blockDim.x + threadIdx.x;
    if (t < Cv) {
        float inv = gamma[t] * rsqrtf(rvar[t] + 1e-5f);
        g_bias[t] = beta[t] - rmean[t] * inv;
    }
    if (t >= WROWS * (WSTRIDE / 2)) return;
    int o = t / (WSTRIDE / 2), c = t % (WSTRIDE / 2);
    float w = 0.f;
    if (c < CIN) {
        int cold = (c < Cv) ? (c + 3) : (c - Cv);
        w = W[o * CIN + cold] * gamma[o] * rsqrtf(rvar[o] + 1e-5f);
    }
    unsigned h;
    asm("cvt.rn.bf16x2.f32 %0, %1, %2;" : "=r"(h) : "f"(0.f), "f"(w));
    float hf = __uint_as_float(h << 16);
    unsigned l;
    asm("cvt.rn.bf16x2.f32 %0, %1, %2;" : "=r"(l) : "f"(0.f), "f"(w - hf));
    g_wh[t] = (unsigned short)(h & 0xffffu);
    g_wl[t] = (unsigned short)(l & 0xffffu);
}

// ---------------------------------------------------------------------------
// H plane build: one thread covers 104 channels (52 b32 words) of one point.
// ---------------------------------------------------------------------------
__device__ __forceinline__ void build_plane(
    int seg, const float2* __restrict__ tj, const float2* __restrict__ tn,
    const float* __restrict__ grow, float dpx, float dpy, float dpz,
    unsigned hdst, bool lo)
{
#pragma unroll
    for (int w4 = 0; w4 < 13; w4++) {
        unsigned words[4];
#pragma unroll
        for (int i = 0; i < 4; i++) {
            int w = w4 * 4 + i;
            int c = seg * 104 + 2 * w;
            float v0, v1;
            if (c < Cv) {
                int d = c >> 6, e = c & 63, f = e & 31;
                float4 a = *(const float4*)(tj + d * 32 + f);
                float4 b = *(const float4*)(tn + d * 32 + f);
                if (e < 32) {          // sin(u - v)
                    v0 = a.x * b.y - a.y * b.x;
                    v1 = a.z * b.w - a.w * b.z;
                } else {               // cos(u - v)
                    v0 = a.y * b.y + a.x * b.x;
                    v1 = a.w * b.w + a.z * b.z;
                }
                float2 g = *(const float2*)(grow + c);
                v0 *= g.x; v1 *= g.y;
            } else if (c == 192) { v0 = dpx; v1 = dpy; }
            else if (c == 194)   { v0 = dpz; v1 = 0.f; }
            else                 { v0 = 0.f; v1 = 0.f; }
            unsigned h;
            asm("cvt.rn.bf16x2.f32 %0, %1, %2;" : "=r"(h) : "f"(v1), "f"(v0));
            if (lo) {
                float h0 = __uint_as_float(h << 16);
                float h1 = __uint_as_float(h & 0xffff0000u);
                asm("cvt.rn.bf16x2.f32 %0, %1, %2;" : "=r"(h) : "f"(v1 - h1), "f"(v0 - h0));
            }
            words[i] = h;
        }
        asm volatile("st.shared.v4.b32 [%0], {%1,%2,%3,%4};"
            :: "r"(hdst + w4 * 16), "r"(words[0]), "r"(words[1]), "r"(words[2]), "r"(words[3]));
    }
}

// ---------------------------------------------------------------------------
// Kernel 4: persistent main. tile = 128 points (4 n x 32 neighbors).
// Warp grid 2(M) x 4(N): warp tile 64 rows x 48 cols.
// ---------------------------------------------------------------------------
__global__ void __launch_bounds__(TPB, 1) local_agg_mma(
    const float* __restrict__ p, const int* __restrict__ idx,
    float* __restrict__ out)
{
    extern __shared__ char sm[];
    const unsigned sb = smem_u32(sm);
    const int t = threadIdx.x;
    const int lane = t & 31, wid = t >> 5;
    const int wm = wid >> 2, wn = wid & 3;
    const int pl = t & 127, seg = t >> 7;

    // load W planes (once per CTA)
    {
        const uint4* s1 = (const uint4*)g_wh;
        const uint4* s2 = (const uint4*)g_wl;
        uint4* d1 = (uint4*)(sm + SM_WH);
        uint4* d2 = (uint4*)(sm + SM_WL);
#pragma unroll 4
        for (int i = t; i < W_BYTES / 16; i += TPB) { d1[i] = s1[i]; d2[i] = s2[i]; }
    }
    __syncthreads();

    // per-lane ldmatrix base addresses (row = lane&15, col-half = lane>>4)
    const unsigned lrow = (unsigned)(lane & 15) * WSTRIDE + ((unsigned)(lane >> 4) << 4);
    const unsigned hA  = sb + SM_H  + (unsigned)wm * 64 * WSTRIDE + lrow;
    const unsigned bWH = sb + SM_WH + (unsigned)wn * 48 * WSTRIDE + lrow;
    const unsigned bWL = sb + SM_WL + (unsigned)wn * 48 * WSTRIDE + lrow;
    float* stage = (float*)(sm + SM_STAGE);

#pragma unroll 1
    for (int tile = blockIdx.x; tile < NTILES; tile += gridDim.x) {
        const int flat = tile * 128 + pl;
        const int b = flat >> 17;
        const int n = (flat >> 5) & (Nv - 1);
        const int j = __ldg(idx + flat);
        const float2* tj = g_trig + (size_t)(b * Nv + j) * 96;
        const float2* tn = g_trig + (size_t)(b * Nv + n) * 96;
        const float* grow = g_xt + (size_t)(b * Nv + j) * Cv;
        float dpx = 0.f, dpy = 0.f, dpz = 0.f;
        if (seg) {
            const float* pj = p + (size_t)(b * Nv + j) * 3;
            const float* pn = p + (size_t)(b * Nv + n) * 3;
            dpx = pj[0] - pn[0]; dpy = pj[1] - pn[1]; dpz = pj[2] - pn[2];
        }
        const unsigned hdst = sb + SM_H + (unsigned)pl * WSTRIDE + (unsigned)seg * 208;

        // ---- build hi plane ----
        build_plane(seg, tj, tn, grow, dpx, dpy, dpz, hdst, false);
        __syncthreads();

        float acc[24][4];
#pragma unroll
        for (int i = 0; i < 24; i++)
#pragma unroll
            for (int q = 0; q < 4; q++) acc[i][q] = 0.f;

        // ---- pass A: Ah*Bh + Ah*Bl ----
#pragma unroll
        for (int s = 0; s < NSTEP; s++) {
            const unsigned ks = (unsigned)s * 32;
            unsigned A[4][4], BH[3][4], BL[3][4];
#pragma unroll
            for (int mf = 0; mf < 4; mf++) LDSM4(A[mf], hA + mf * 16 * WSTRIDE + ks);
#pragma unroll
            for (int q = 0; q < 3; q++) {
                LDSM4(BH[q], bWH + q * 16 * WSTRIDE + ks);
                LDSM4(BL[q], bWL + q * 16 * WSTRIDE + ks);
            }
#pragma unroll
            for (int mf = 0; mf < 4; mf++)
#pragma unroll
                for (int q = 0; q < 3; q++) {
                    MMA(acc[mf * 6 + 2 * q],     A[mf], BH[q][0], BH[q][2]);
                    MMA(acc[mf * 6 + 2 * q + 1], A[mf], BH[q][1], BH[q][3]);
                }
#pragma unroll
            for (int mf = 0; mf < 4; mf++)
#pragma unroll
                for (int q = 0; q < 3; q++) {
                    MMA(acc[mf * 6 + 2 * q],     A[mf], BL[q][0], BL[q][2]);
                    MMA(acc[mf * 6 + 2 * q + 1], A[mf], BL[q][1], BL[q][3]);
                }
        }
        __syncthreads();

        // ---- build lo plane (recompute; overwrite H) ----
        build_plane(seg, tj, tn, grow, dpx, dpy, dpz, hdst, true);
        __syncthreads();

        // ---- pass B: Al*Bh ----
#pragma unroll
        for (int s = 0; s < NSTEP; s++) {
            const unsigned ks = (unsigned)s * 32;
            unsigned A[4][4], BH[3][4];
#pragma unroll
            for (int mf = 0; mf < 4; mf++) LDSM4(A[mf], hA + mf * 16 * WSTRIDE + ks);
#pragma unroll
            for (int q = 0; q < 3; q++) LDSM4(BH[q], bWH + q * 16 * WSTRIDE + ks);
#pragma unroll
            for (int mf = 0; mf < 4; mf++)
#pragma unroll
                for (int q = 0; q < 3; q++) {
                    MMA(acc[mf * 6 + 2 * q],     A[mf], BH[q][0], BH[q][2]);
                    MMA(acc[mf * 6 + 2 * q + 1], A[mf], BH[q][1], BH[q][3]);
                }
        }

        // ---- epilogue: max over 32 rows per group, stage, store ----
#pragma unroll
        for (int gg = 0; gg < 2; gg++) {
            const int group = wm * 2 + gg;
#pragma unroll
            for (int nf = 0; nf < 6; nf++) {
                const float* a0 = acc[(2 * gg) * 6 + nf];
                const float* a1 = acc[(2 * gg + 1) * 6 + nf];
                float v0 = fmaxf(fmaxf(a0[0], a0[2]), fmaxf(a1[0], a1[2]));
                float v1 = fmaxf(fmaxf(a0[1], a0[3]), fmaxf(a1[1], a1[3]));
#pragma unroll
                for (int off = 4; off < 32; off <<= 1) {
                    v0 = fmaxf(v0, __shfl_xor_sync(0xffffffffu, v0, off));
                    v1 = fmaxf(v1, __shfl_xor_sync(0xffffffffu, v1, off));
                }
                if (lane < 4)
                    *(float2*)(stage + group * Cv + wn * 48 + nf * 8 + 2 * lane) =
                        make_float2(v0, v1);
            }
        }
        __syncthreads();

        if (t < Cv) {
            const float bias = __ldg(g_bias + t);
            float4 o4;
            o4.x = fmaxf(stage[0 * Cv + t] + bias, 0.f);
            o4.y = fmaxf(stage[1 * Cv + t] + bias, 0.f);
            o4.z = fmaxf(stage[2 * Cv + t] + bias, 0.f);
            o4.w = fmaxf(stage[3 * Cv + t] + bias, 0.f);
            const int bo = tile >> 10;
            const int n0 = (tile & 1023) << 2;
            *(float4*)(out + ((size_t)(bo * Cv + t)) * Nv + n0) = o4;
        }
        __syncthreads();
    }
}

// ---------------------------------------------------------------------------
extern "C" void kernel_launch(void* const* d_in, const int* in_sizes, int n_in,
                              void* d_out, int out_size) {
    const float* p     = (const float*)d_in[0];
    const float* x     = (const float*)d_in[1];
    const int*   idx   = (const int*)d_in[2];
    const float* W     = (const float*)d_in[3];
    const float* gamma = (const float*)d_in[4];
    const float* beta  = (const float*)d_in[5];
    const float* rmean = (const float*)d_in[6];
    const float* rvar  = (const float*)d_in[7];
    float* out = (float*)d_out;

    cudaFuncSetAttribute(local_agg_mma, cudaFuncAttributeMaxDynamicSharedMemorySize, SMEM_TOTAL);

    dim3 tb(32, 8);
    dim3 tg(Nv / 32, Cv / 32, Bv);
    transpose_add1<<<tg, tb>>>(x);
    trig_pre<<<(Bv * Nv * 96 + 255) / 256, 256>>>(p);
    prep_w<<<(WROWS * (WSTRIDE / 2) + 255) / 256, 256>>>(W, gamma, beta, rmean, rvar);
    local_agg_mma<<<GRID_MAIN, TPB, SMEM_TOTAL>>>(p, idx, out);
}

// round 4
// speedup vs baseline: 1.6526x; 1.6526x over previous
#include <cuda_runtime.h>
#include <cuda_bf16.h>
#include <cstdint>

#define Bv 4
#define Nv 4096
#define Cv 192
#define CIN 195
#define NSTEP 13
#define WSTRIDE 432                   // 27*16B; 108 words = 12 mod 32 -> conflict-free LDSM
#define W_BYTES (192 * WSTRIDE)       // 82944
#define H_BYTES (64 * WSTRIDE)        // 27648
#define SM_WH 0
#define SM_WL W_BYTES
#define SM_HH (2 * W_BYTES)
#define SM_HL (2 * W_BYTES + H_BYTES)
#define SM_STAGE (2 * W_BYTES + 2 * H_BYTES)
#define SMEM_TOTAL (SM_STAGE + 2 * Cv * 4)   // 222720
#define NTILES (Bv * Nv / 2)          // 8192 tiles of 64 points (2 n each)
#define GRID_MAIN 152
#define TPB 256

// ---------------- device scratch ----------------
__device__ float g_xt[Bv * Nv * Cv];              // (x+1), [b][n][c]
__device__ float2 g_trig[Bv * Nv * 3 * 32];       // (sin, cos)(50*p*m_f)
__device__ unsigned short g_wh[192 * (WSTRIDE / 2)];
__device__ unsigned short g_wl[192 * (WSTRIDE / 2)];
__device__ float g_bias[Cv];

// ---------------- PTX helpers ----------------
__device__ __forceinline__ unsigned smem_u32(const void* p) {
    unsigned a;
    asm("{ .reg .u64 t; cvta.to.shared.u64 t, %1; cvt.u32.u64 %0, t; }" : "=r"(a) : "l"(p));
    return a;
}
#define LDSM4(r, a) \
    asm volatile("ldmatrix.sync.aligned.m8n8.x4.shared.b16 {%0,%1,%2,%3}, [%4];" \
        : "=r"((r)[0]), "=r"((r)[1]), "=r"((r)[2]), "=r"((r)[3]) : "r"(a))
#define MMA(d, a, b0, b1) \
    asm volatile("mma.sync.aligned.m16n8k16.row.col.f32.bf16.bf16.f32 " \
        "{%0,%1,%2,%3},{%4,%5,%6,%7},{%8,%9},{%0,%1,%2,%3};" \
        : "+f"((d)[0]), "+f"((d)[1]), "+f"((d)[2]), "+f"((d)[3]) \
        : "r"((a)[0]), "r"((a)[1]), "r"((a)[2]), "r"((a)[3]), "r"(b0), "r"(b1))

// ---------------------------------------------------------------------------
// Kernel 1: transpose x [B,C,N] -> xt [B,N,C], fused +1
// ---------------------------------------------------------------------------
__global__ void transpose_add1(const float* __restrict__ x) {
    __shared__ float tile[32][33];
    int n0 = blockIdx.x * 32, c0 = blockIdx.y * 32, b = blockIdx.z;
    int tx = threadIdx.x, ty = threadIdx.y;
#pragma unroll
    for (int i = 0; i < 4; i++)
        tile[ty + i * 8][tx] = x[((size_t)b * Cv + c0 + ty + i * 8) * Nv + n0 + tx];
    __syncthreads();
#pragma unroll
    for (int i = 0; i < 4; i++)
        g_xt[((size_t)b * Nv + n0 + ty + i * 8) * Cv + c0 + tx] = tile[tx][ty + i * 8] + 1.0f;
}

// ---------------------------------------------------------------------------
// Kernel 2: per-point trig table  (sin, cos)(50 * p[b][n][d] * 500^(-f/32))
// ---------------------------------------------------------------------------
__global__ void trig_pre(const float* __restrict__ p) {
    int t = blockIdx.x * blockDim.x + threadIdx.x;
    if (t >= Bv * Nv * 96) return;
    int f = t & 31;
    int pd = t >> 5;
    float m = (float)exp2(-(double)f * (8.9657842846620870436 / 32.0));
    float arg = 50.0f * p[pd] * m;
    float s, c;
    sincosf(arg, &s, &c);
    g_trig[t] = make_float2(s, c);
}

// ---------------------------------------------------------------------------
// Kernel 3: fold BN into W, bf16 hi/lo split; channel order: pe 0..191, dp 192..194
// ---------------------------------------------------------------------------
__global__ void prep_w(const float* __restrict__ W, const float* __restrict__ gamma,
                       const float* __restrict__ beta, const float* __restrict__ rmean,
                       const float* __restrict__ rvar) {
    int t = blockIdx.x * blockDim.x + threadIdx.x;
    if (t < Cv) {
        float inv = gamma[t] * rsqrtf(rvar[t] + 1e-5f);
        g_bias[t] = beta[t] - rmean[t] * inv;
    }
    if (t >= 192 * (WSTRIDE / 2)) return;
    int o = t / (WSTRIDE / 2), c = t % (WSTRIDE / 2);
    float w = 0.f;
    if (c < CIN) {
        int cold = (c < Cv) ? (c + 3) : (c - Cv);
        w = W[o * CIN + cold] * gamma[o] * rsqrtf(rvar[o] + 1e-5f);
    }
    unsigned h;
    asm("cvt.rn.bf16x2.f32 %0, %1, %2;" : "=r"(h) : "f"(0.f), "f"(w));
    float hf = __uint_as_float(h << 16);
    unsigned l;
    asm("cvt.rn.bf16x2.f32 %0, %1, %2;" : "=r"(l) : "f"(0.f), "f"(w - hf));
    g_wh[t] = (unsigned short)(h & 0xffffu);
    g_wl[t] = (unsigned short)(l & 0xffffu);
}

// ---------------------------------------------------------------------------
// Kernel 4: persistent main. tile = 64 points (2 n x 32 neighbors).
// Warp grid 2(M) x 4(N): warp tile 32 rows x 48 cols. acc = 48 regs/thread.
// Both H planes + both W planes resident in smem -> single build per tile.
// ---------------------------------------------------------------------------
__global__ void __launch_bounds__(TPB, 1) local_agg_mma(
    const float* __restrict__ p, const int* __restrict__ idx,
    float* __restrict__ out)
{
    extern __shared__ char sm[];
    const unsigned sb = smem_u32(sm);
    const int t = threadIdx.x;
    const int lane = t & 31, wid = t >> 5;
    const int wm = wid >> 2, wn = wid & 3;    // 2 x 4 warp grid

    // load W planes once
    {
        const uint4* s1 = (const uint4*)g_wh;
        const uint4* s2 = (const uint4*)g_wl;
        uint4* d1 = (uint4*)(sm + SM_WH);
        uint4* d2 = (uint4*)(sm + SM_WL);
#pragma unroll 4
        for (int i = t; i < W_BYTES / 16; i += TPB) { d1[i] = s1[i]; d2[i] = s2[i]; }
    }
    __syncthreads();

    const unsigned lrow = (unsigned)(lane & 15) * WSTRIDE + ((unsigned)(lane >> 4) << 4);
    const unsigned hAH = sb + SM_HH + (unsigned)wm * 32 * WSTRIDE + lrow;
    const unsigned hAL = sb + SM_HL + (unsigned)wm * 32 * WSTRIDE + lrow;
    const unsigned bWH = sb + SM_WH + (unsigned)wn * 48 * WSTRIDE + lrow;
    const unsigned bWL = sb + SM_WL + (unsigned)wn * 48 * WSTRIDE + lrow;
    float* stage = (float*)(sm + SM_STAGE);

    const int pl = t >> 2;                    // point within tile (0..63)
    const int q = t & 3;                      // channel quarter (52 ch each)

#pragma unroll 1
    for (int tile = blockIdx.x; tile < NTILES; tile += GRID_MAIN) {
        // ---- build both H planes (64 points x 208 ch, hi+lo in one pass) ----
        {
            const int flat = tile * 64 + pl;
            const int b = flat >> 17;
            const int n = (flat >> 5) & (Nv - 1);
            const int j = __ldg(idx + flat);
            const float2* tj = g_trig + (size_t)(b * Nv + j) * 96;
            const float2* tn = g_trig + (size_t)(b * Nv + n) * 96;
            const float* grow = g_xt + (size_t)(b * Nv + j) * Cv;
            float dpx = 0.f, dpy = 0.f, dpz = 0.f;
            if (q == 3) {
                const float* pj = p + (size_t)(b * Nv + j) * 3;
                const float* pn = p + (size_t)(b * Nv + n) * 3;
                dpx = pj[0] - pn[0]; dpy = pj[1] - pn[1]; dpz = pj[2] - pn[2];
            }
            const unsigned hdst = sb + SM_HH + (unsigned)pl * WSTRIDE + (unsigned)q * 104;
            const unsigned ldst = sb + SM_HL + (unsigned)pl * WSTRIDE + (unsigned)q * 104;
#pragma unroll
            for (int w2 = 0; w2 < 13; w2++) {
                unsigned hw[2], lw[2];
#pragma unroll
                for (int i = 0; i < 2; i++) {
                    const int c = q * 52 + (w2 * 2 + i) * 2;
                    float v0, v1;
                    if (c < Cv) {
                        int d = c >> 6, e = c & 63, f = e & 31;
                        float4 a = *(const float4*)(tj + d * 32 + f);
                        float4 bb = *(const float4*)(tn + d * 32 + f);
                        if (e < 32) {  // sin(u-v)
                            v0 = a.x * bb.y - a.y * bb.x;
                            v1 = a.z * bb.w - a.w * bb.z;
                        } else {       // cos(u-v)
                            v0 = a.y * bb.y + a.x * bb.x;
                            v1 = a.w * bb.w + a.z * bb.z;
                        }
                        float2 g = *(const float2*)(grow + c);
                        v0 *= g.x; v1 *= g.y;
                    } else if (c == 192) { v0 = dpx; v1 = dpy; }
                    else if (c == 194)   { v0 = dpz; v1 = 0.f; }
                    else                 { v0 = 0.f; v1 = 0.f; }
                    unsigned h;
                    asm("cvt.rn.bf16x2.f32 %0, %1, %2;" : "=r"(h) : "f"(v1), "f"(v0));
                    float h0 = __uint_as_float(h << 16);
                    float h1 = __uint_as_float(h & 0xffff0000u);
                    unsigned l;
                    asm("cvt.rn.bf16x2.f32 %0, %1, %2;" : "=r"(l) : "f"(v1 - h1), "f"(v0 - h0));
                    hw[i] = h; lw[i] = l;
                }
                asm volatile("st.shared.v2.b32 [%0], {%1,%2};" :: "r"(hdst + w2 * 8), "r"(hw[0]), "r"(hw[1]));
                asm volatile("st.shared.v2.b32 [%0], {%1,%2};" :: "r"(ldst + w2 * 8), "r"(lw[0]), "r"(lw[1]));
            }
        }
        __syncthreads();

        // ---- k-loop: 3 split products, acc 2M x 6N frags ----
        float acc[12][4];
#pragma unroll
        for (int i = 0; i < 12; i++)
#pragma unroll
            for (int r = 0; r < 4; r++) acc[i][r] = 0.f;

#pragma unroll 1
        for (int s = 0; s < NSTEP; s++) {
            const unsigned ks = (unsigned)s * 32;
            unsigned AH[2][4], AL[2][4], WH[3][4], WL[3][4];
#pragma unroll
            for (int mf = 0; mf < 2; mf++) {
                LDSM4(AH[mf], hAH + mf * 16 * WSTRIDE + ks);
                LDSM4(AL[mf], hAL + mf * 16 * WSTRIDE + ks);
            }
#pragma unroll
            for (int qq = 0; qq < 3; qq++) {
                LDSM4(WH[qq], bWH + qq * 16 * WSTRIDE + ks);
                LDSM4(WL[qq], bWL + qq * 16 * WSTRIDE + ks);
            }
#pragma unroll
            for (int mf = 0; mf < 2; mf++)
#pragma unroll
                for (int qq = 0; qq < 3; qq++) {
                    MMA(acc[mf * 6 + 2 * qq],     AH[mf], WH[qq][0], WH[qq][2]);
                    MMA(acc[mf * 6 + 2 * qq + 1], AH[mf], WH[qq][1], WH[qq][3]);
                    MMA(acc[mf * 6 + 2 * qq],     AH[mf], WL[qq][0], WL[qq][2]);
                    MMA(acc[mf * 6 + 2 * qq + 1], AH[mf], WL[qq][1], WL[qq][3]);
                    MMA(acc[mf * 6 + 2 * qq],     AL[mf], WH[qq][0], WH[qq][2]);
                    MMA(acc[mf * 6 + 2 * qq + 1], AL[mf], WH[qq][1], WH[qq][3]);
                }
        }

        // ---- epilogue: max over 32 rows (= 32 neighbors of one n) ----
#pragma unroll
        for (int nf = 0; nf < 6; nf++) {
            const float* a0 = acc[nf];          // rows 0-15 of warp half
            const float* a1 = acc[6 + nf];      // rows 16-31
            float v0 = fmaxf(fmaxf(a0[0], a0[2]), fmaxf(a1[0], a1[2]));
            float v1 = fmaxf(fmaxf(a0[1], a0[3]), fmaxf(a1[1], a1[3]));
#pragma unroll
            for (int off = 4; off < 32; off <<= 1) {
                v0 = fmaxf(v0, __shfl_xor_sync(0xffffffffu, v0, off));
                v1 = fmaxf(v1, __shfl_xor_sync(0xffffffffu, v1, off));
            }
            if (lane < 4)
                *(float2*)(stage + wm * Cv + wn * 48 + nf * 8 + 2 * lane) = make_float2(v0, v1);
        }
        __syncthreads();

        if (t < Cv) {
            const float bias = __ldg(g_bias + t);
            float2 o2;
            o2.x = fmaxf(stage[0 * Cv + t] + bias, 0.f);
            o2.y = fmaxf(stage[1 * Cv + t] + bias, 0.f);
            const int bo = tile >> 11;
            const int n0 = (tile * 2) & (Nv - 1);
            *(float2*)(out + ((size_t)(bo * Cv + t)) * Nv + n0) = o2;
        }
        __syncthreads();
    }
}

// ---------------------------------------------------------------------------
extern "C" void kernel_launch(void* const* d_in, const int* in_sizes, int n_in,
                              void* d_out, int out_size) {
    const float* p     = (const float*)d_in[0];
    const float* x     = (const float*)d_in[1];
    const int*   idx   = (const int*)d_in[2];
    const float* W     = (const float*)d_in[3];
    const float* gamma = (const float*)d_in[4];
    const float* beta  = (const float*)d_in[5];
    const float* rmean = (const float*)d_in[6];
    const float* rvar  = (const float*)d_in[7];
    float* out = (float*)d_out;

    cudaFuncSetAttribute(local_agg_mma, cudaFuncAttributeMaxDynamicSharedMemorySize, SMEM_TOTAL);

    dim3 tb(32, 8);
    dim3 tg(Nv / 32, Cv / 32, Bv);
    transpose_add1<<<tg, tb>>>(x);
    trig_pre<<<(Bv * Nv * 96 + 255) / 256, 256>>>(p);
    prep_w<<<(192 * (WSTRIDE / 2) + 255) / 256, 256>>>(W, gamma, beta, rmean, rvar);
    local_agg_mma<<<GRID_MAIN, TPB, SMEM_TOTAL>>>(p, idx, out);
}

// round 5
// speedup vs baseline: 3.1966x; 1.9342x over previous
#include <cuda_runtime.h>
#include <cuda_fp16.h>
#include <cstdint>

#define Bv 4
#define Nv 4096
#define Cv 192
#define CIN 195
#define NSTEP 13
#define WSTRIDE 432                   // 108 words = 12 mod 32 -> conflict-free LDSM
#define W_BYTES (192 * WSTRIDE)       // 82944
#define H_BYTES (64 * WSTRIDE)        // 27648
#define SM_WH 0
#define SM_HH W_BYTES
#define SM_HL (W_BYTES + H_BYTES)
#define SM_STAGE (W_BYTES + 2 * H_BYTES)
#define SMEM_TOTAL (SM_STAGE + 4 * Cv * 4)   // 141312
#define NTILES (Bv * Nv / 2)          // 8192 tiles of 64 points (2 n each)
#define GRID_MAIN 152
#define TPB 512

// ---------------- device scratch ----------------
__device__ float g_xt[Bv * Nv * Cv];              // (x+1), [b][n][c]
__device__ float2 g_trig[Bv * Nv * 3 * 32];       // (sin, cos)(50*p*m_f)
__device__ __half g_wh[192 * (WSTRIDE / 2)];      // fp16 BN-folded W
__device__ float g_bias[Cv];

// ---------------- PTX helpers ----------------
__device__ __forceinline__ unsigned smem_u32(const void* p) {
    unsigned a;
    asm("{ .reg .u64 t; cvta.to.shared.u64 t, %1; cvt.u32.u64 %0, t; }" : "=r"(a) : "l"(p));
    return a;
}
#define LDSM4(r, a) \
    asm volatile("ldmatrix.sync.aligned.m8n8.x4.shared.b16 {%0,%1,%2,%3}, [%4];" \
        : "=r"((r)[0]), "=r"((r)[1]), "=r"((r)[2]), "=r"((r)[3]) : "r"(a))
#define MMA(d, a, b0, b1) \
    asm volatile("mma.sync.aligned.m16n8k16.row.col.f32.f16.f16.f32 " \
        "{%0,%1,%2,%3},{%4,%5,%6,%7},{%8,%9},{%0,%1,%2,%3};" \
        : "+f"((d)[0]), "+f"((d)[1]), "+f"((d)[2]), "+f"((d)[3]) \
        : "r"((a)[0]), "r"((a)[1]), "r"((a)[2]), "r"((a)[3]), "r"(b0), "r"(b1))

// ---------------------------------------------------------------------------
// Kernel 1: transpose x [B,C,N] -> xt [B,N,C], fused +1
// ---------------------------------------------------------------------------
__global__ void transpose_add1(const float* __restrict__ x) {
    __shared__ float tile[32][33];
    int n0 = blockIdx.x * 32, c0 = blockIdx.y * 32, b = blockIdx.z;
    int tx = threadIdx.x, ty = threadIdx.y;
#pragma unroll
    for (int i = 0; i < 4; i++)
        tile[ty + i * 8][tx] = x[((size_t)b * Cv + c0 + ty + i * 8) * Nv + n0 + tx];
    __syncthreads();
#pragma unroll
    for (int i = 0; i < 4; i++)
        g_xt[((size_t)b * Nv + n0 + ty + i * 8) * Cv + c0 + tx] = tile[tx][ty + i * 8] + 1.0f;
}

// ---------------------------------------------------------------------------
// Kernel 2: per-point trig table  (sin, cos)(50 * p[b][n][d] * 500^(-f/32))
// ---------------------------------------------------------------------------
__global__ void trig_pre(const float* __restrict__ p) {
    int t = blockIdx.x * blockDim.x + threadIdx.x;
    if (t >= Bv * Nv * 96) return;
    int f = t & 31;
    int pd = t >> 5;
    float m = (float)exp2(-(double)f * (8.9657842846620870436 / 32.0));
    float arg = 50.0f * p[pd] * m;
    float s, c;
    sincosf(arg, &s, &c);
    g_trig[t] = make_float2(s, c);
}

// ---------------------------------------------------------------------------
// Kernel 3: fold BN into W (fp16); channel order: pe 0..191, dp 192..194, pad 0
// ---------------------------------------------------------------------------
__global__ void prep_w(const float* __restrict__ W, const float* __restrict__ gamma,
                       const float* __restrict__ beta, const float* __restrict__ rmean,
                       const float* __restrict__ rvar) {
    int t = blockIdx.x * blockDim.x + threadIdx.x;
    if (t < Cv) {
        float inv = gamma[t] * rsqrtf(rvar[t] + 1e-5f);
        g_bias[t] = beta[t] - rmean[t] * inv;
    }
    if (t >= 192 * (WSTRIDE / 2)) return;
    int o = t / (WSTRIDE / 2), c = t % (WSTRIDE / 2);
    float w = 0.f;
    if (c < CIN) {
        int cold = (c < Cv) ? (c + 3) : (c - Cv);
        w = W[o * CIN + cold] * gamma[o] * rsqrtf(rvar[o] + 1e-5f);
    }
    g_wh[t] = __float2half_rn(w);
}

// ---------------------------------------------------------------------------
// Kernel 4: persistent main. tile = 64 points (2 n x 32 neighbors).
// 512 threads, warp grid 4(M) x 4(N): warp tile 16 rows x 48 cols, acc 24 regs.
// 2 fp16 split-products: Ah*W + Al*W. Pipelined fully-unrolled k-loop.
// ---------------------------------------------------------------------------
__global__ void __launch_bounds__(TPB, 1) local_agg_mma(
    const float* __restrict__ p, const int* __restrict__ idx,
    float* __restrict__ out)
{
    extern __shared__ char sm[];
    const unsigned sb = smem_u32(sm);
    const int t = threadIdx.x;
    const int lane = t & 31, wid = t >> 5;
    const int wm = wid >> 2, wn = wid & 3;    // 4 x 4 warp grid

    // load W plane once
    {
        const uint4* s1 = (const uint4*)g_wh;
        uint4* d1 = (uint4*)(sm + SM_WH);
#pragma unroll 4
        for (int i = t; i < W_BYTES / 16; i += TPB) d1[i] = s1[i];
    }
    __syncthreads();

    const unsigned lrow = (unsigned)(lane & 15) * WSTRIDE + ((unsigned)(lane >> 4) << 4);
    const unsigned hAH = sb + SM_HH + (unsigned)wm * 16 * WSTRIDE + lrow;
    const unsigned hAL = sb + SM_HL + (unsigned)wm * 16 * WSTRIDE + lrow;
    const unsigned bWH = sb + SM_WH + (unsigned)wn * 48 * WSTRIDE + lrow;
    float* stage = (float*)(sm + SM_STAGE);

    const int pl = t >> 3;                    // point within tile (0..63)
    const int sg = t & 7;                     // channel segment (26 ch each)

#pragma unroll 1
    for (int tile = blockIdx.x; tile < NTILES; tile += GRID_MAIN) {
        // ---- build H hi+lo planes (64 points x 208 ch) ----
        {
            const int flat = tile * 64 + pl;
            const int b = flat >> 17;
            const int n = (flat >> 5) & (Nv - 1);
            const int j = __ldg(idx + flat);
            const float2* tj = g_trig + (size_t)(b * Nv + j) * 96;
            const float2* tn = g_trig + (size_t)(b * Nv + n) * 96;
            const float* grow = g_xt + (size_t)(b * Nv + j) * Cv;
            float dpx = 0.f, dpy = 0.f, dpz = 0.f;
            if (sg == 7) {
                const float* pj = p + (size_t)(b * Nv + j) * 3;
                const float* pn = p + (size_t)(b * Nv + n) * 3;
                dpx = pj[0] - pn[0]; dpy = pj[1] - pn[1]; dpz = pj[2] - pn[2];
            }
            __half2* hdst = (__half2*)(sm + SM_HH + pl * WSTRIDE + sg * 52);
            __half2* ldst = (__half2*)(sm + SM_HL + pl * WSTRIDE + sg * 52);
#pragma unroll
            for (int i = 0; i < 13; i++) {
                const int c = sg * 26 + 2 * i;
                float v0, v1;
                if (c < Cv) {
                    int d = c >> 6, e = c & 63, f = e & 31;
                    float4 a = *(const float4*)(tj + d * 32 + f);
                    float4 bb = *(const float4*)(tn + d * 32 + f);
                    if (e < 32) {  // sin(u-v)
                        v0 = a.x * bb.y - a.y * bb.x;
                        v1 = a.z * bb.w - a.w * bb.z;
                    } else {       // cos(u-v)
                        v0 = a.y * bb.y + a.x * bb.x;
                        v1 = a.w * bb.w + a.z * bb.z;
                    }
                    float2 g = *(const float2*)(grow + c);
                    v0 *= g.x; v1 *= g.y;
                } else if (c == 192) { v0 = dpx; v1 = dpy; }
                else if (c == 194)   { v0 = dpz; v1 = 0.f; }
                else                 { v0 = 0.f; v1 = 0.f; }
                __half2 h = __float22half2_rn(make_float2(v0, v1));
                float r0 = v0 - __half2float(__low2half(h));
                float r1 = v1 - __half2float(__high2half(h));
                hdst[i] = h;
                ldst[i] = __float22half2_rn(make_float2(r0, r1));
            }
        }
        __syncthreads();

        // ---- pipelined k-loop: Ah*W + Al*W, double-buffered frags ----
        float acc[6][4];
#pragma unroll
        for (int i = 0; i < 6; i++)
#pragma unroll
            for (int r = 0; r < 4; r++) acc[i][r] = 0.f;

        unsigned AH[2][4], AL[2][4], WF[2][3][4];
        LDSM4(AH[0], hAH);
        LDSM4(AL[0], hAL);
#pragma unroll
        for (int q = 0; q < 3; q++) LDSM4(WF[0][q], bWH + q * 16 * WSTRIDE);

#pragma unroll
        for (int s = 0; s < NSTEP; s++) {
            const int cur = s & 1, nxt = cur ^ 1;
            if (s + 1 < NSTEP) {
                const unsigned ks = (unsigned)(s + 1) * 32;
                LDSM4(AH[nxt], hAH + ks);
                LDSM4(AL[nxt], hAL + ks);
#pragma unroll
                for (int q = 0; q < 3; q++) LDSM4(WF[nxt][q], bWH + q * 16 * WSTRIDE + ks);
            }
#pragma unroll
            for (int q = 0; q < 3; q++) {
                MMA(acc[2 * q],     AH[cur], WF[cur][q][0], WF[cur][q][2]);
                MMA(acc[2 * q + 1], AH[cur], WF[cur][q][1], WF[cur][q][3]);
                MMA(acc[2 * q],     AL[cur], WF[cur][q][0], WF[cur][q][2]);
                MMA(acc[2 * q + 1], AL[cur], WF[cur][q][1], WF[cur][q][3]);
            }
        }

        // ---- epilogue: max over warp's 16 rows, stage per wm ----
#pragma unroll
        for (int nf = 0; nf < 6; nf++) {
            float v0 = fmaxf(acc[nf][0], acc[nf][2]);
            float v1 = fmaxf(acc[nf][1], acc[nf][3]);
#pragma unroll
            for (int off = 4; off < 32; off <<= 1) {
                v0 = fmaxf(v0, __shfl_xor_sync(0xffffffffu, v0, off));
                v1 = fmaxf(v1, __shfl_xor_sync(0xffffffffu, v1, off));
            }
            if (lane < 4)
                *(float2*)(stage + wm * Cv + wn * 48 + nf * 8 + 2 * lane) = make_float2(v0, v1);
        }
        __syncthreads();

        if (t < Cv) {
            const float bias = __ldg(g_bias + t);
            float2 o2;
            o2.x = fmaxf(fmaxf(stage[0 * Cv + t], stage[1 * Cv + t]) + bias, 0.f);
            o2.y = fmaxf(fmaxf(stage[2 * Cv + t], stage[3 * Cv + t]) + bias, 0.f);
            const int bo = tile >> 11;
            const int n0 = (tile * 2) & (Nv - 1);
            *(float2*)(out + ((size_t)(bo * Cv + t)) * Nv + n0) = o2;
        }
        // no extra sync needed: next build writes only H planes; the build-side
        // __syncthreads() orders stage reads before the next epilogue's writes.
        __syncthreads();
    }
}

// ---------------------------------------------------------------------------
extern "C" void kernel_launch(void* const* d_in, const int* in_sizes, int n_in,
                              void* d_out, int out_size) {
    const float* p     = (const float*)d_in[0];
    const float* x     = (const float*)d_in[1];
    const int*   idx   = (const int*)d_in[2];
    const float* W     = (const float*)d_in[3];
    const float* gamma = (const float*)d_in[4];
    const float* beta  = (const float*)d_in[5];
    const float* rmean = (const float*)d_in[6];
    const float* rvar  = (const float*)d_in[7];
    float* out = (float*)d_out;

    cudaFuncSetAttribute(local_agg_mma, cudaFuncAttributeMaxDynamicSharedMemorySize, SMEM_TOTAL);

    dim3 tb(32, 8);
    dim3 tg(Nv / 32, Cv / 32, Bv);
    transpose_add1<<<tg, tb>>>(x);
    trig_pre<<<(Bv * Nv * 96 + 255) / 256, 256>>>(p);
    prep_w<<<(192 * (WSTRIDE / 2) + 255) / 256, 256>>>(W, gamma, beta, rmean, rvar);
    local_agg_mma<<<GRID_MAIN, TPB, SMEM_TOTAL>>>(p, idx, out);
}

// round 6
// speedup vs baseline: 3.6643x; 1.1463x over previous
#include <cuda_runtime.h>
#include <cuda_fp16.h>
#include <cstdint>

#define Bv 4
#define Nv 4096
#define Cv 192
#define CIN 195
#define NSTEP 13
#define WSTRIDE 432                   // 108 words = 12 mod 32 -> conflict-free LDSM
#define W_BYTES (192 * WSTRIDE)       // 82944
#define H_BYTES (64 * WSTRIDE)        // 27648
#define SM_WH 0
#define SM_HH W_BYTES
#define SM_HL (W_BYTES + H_BYTES)
#define SM_STAGE (W_BYTES + 2 * H_BYTES)          // 138240
#define SM_SNC (SM_STAGE + 4 * Cv * 4)            // 141312
#define SMEM_TOTAL (SM_SNC + 2 * 200 * 4)         // 142912
#define NTILES (Bv * Nv / 2)          // 8192 tiles of 64 points (2 n each)
#define GRID_MAIN 152
#define TPB 512
#define ROWF 584                      // floats per table row (2336 B)

// ---------------- device scratch ----------------
__device__ float g_xt[Bv * Nv * Cv];              // (x+1), [b][n][c]
__device__ float g_tab[Bv * Nv * ROWF];           // per-point: A1[192] A2[192] S[96] C[96] p[3] pad
__device__ __half g_wh[192 * (WSTRIDE / 2)];      // fp16 BN-folded W
__device__ float g_bias[Cv];

// ---------------- PTX helpers ----------------
__device__ __forceinline__ unsigned smem_u32(const void* p) {
    unsigned a;
    asm("{ .reg .u64 t; cvta.to.shared.u64 t, %1; cvt.u32.u64 %0, t; }" : "=r"(a) : "l"(p));
    return a;
}
#define LDSM4(r, a) \
    asm volatile("ldmatrix.sync.aligned.m8n8.x4.shared.b16 {%0,%1,%2,%3}, [%4];" \
        : "=r"((r)[0]), "=r"((r)[1]), "=r"((r)[2]), "=r"((r)[3]) : "r"(a))
#define MMA(d, a, b0, b1) \
    asm volatile("mma.sync.aligned.m16n8k16.row.col.f32.f16.f16.f32 " \
        "{%0,%1,%2,%3},{%4,%5,%6,%7},{%8,%9},{%0,%1,%2,%3};" \
        : "+f"((d)[0]), "+f"((d)[1]), "+f"((d)[2]), "+f"((d)[3]) \
        : "r"((a)[0]), "r"((a)[1]), "r"((a)[2]), "r"((a)[3]), "r"(b0), "r"(b1))

// ---------------------------------------------------------------------------
// Kernel 1: transpose x [B,C,N] -> xt [B,N,C], fused +1
// ---------------------------------------------------------------------------
__global__ void transpose_add1(const float* __restrict__ x) {
    __shared__ float tile[32][33];
    int n0 = blockIdx.x * 32, c0 = blockIdx.y * 32, b = blockIdx.z;
    int tx = threadIdx.x, ty = threadIdx.y;
#pragma unroll
    for (int i = 0; i < 4; i++)
        tile[ty + i * 8][tx] = x[((size_t)b * Cv + c0 + ty + i * 8) * Nv + n0 + tx];
    __syncthreads();
#pragma unroll
    for (int i = 0; i < 4; i++)
        g_xt[((size_t)b * Nv + n0 + ty + i * 8) * Cv + c0 + tx] = tile[tx][ty + i * 8] + 1.0f;
}

// ---------------------------------------------------------------------------
// Kernel 2: per-point table.  thread = (pt, f).
//   A1[c] = sin(50*p_d*m_f) * g[c],  A2[c] = cos(..) * g[c]  for c in {d*64+f, d*64+32+f}
//   S[d*32+f], C[d*32+f] raw, p tail.
// ---------------------------------------------------------------------------
__global__ void table_pre(const float* __restrict__ p) {
    int t = blockIdx.x * blockDim.x + threadIdx.x;
    if (t >= Bv * Nv * 32) return;
    int f = t & 31, pt = t >> 5;
    float m = (float)exp2(-(double)f * (8.9657842846620870436 / 32.0));
    float* row = g_tab + (size_t)pt * ROWF;
    const float* xr = g_xt + (size_t)pt * Cv;
#pragma unroll
    for (int d = 0; d < 3; d++) {
        float s, c;
        sincosf(50.0f * p[pt * 3 + d] * m, &s, &c);
        int c1 = d * 64 + f, c2 = c1 + 32, i96 = d * 32 + f;
        float g1 = xr[c1], g2 = xr[c2];
        row[c1] = s * g1;        row[c2] = s * g2;        // A1
        row[192 + c1] = c * g1;  row[192 + c2] = c * g2;  // A2
        row[384 + i96] = s;      row[480 + i96] = c;      // raw S, C
    }
    if (f < 3) row[576 + f] = p[pt * 3 + f];
    if (f == 3) { row[579] = 0.f; row[580] = 0.f; row[581] = 0.f; row[582] = 0.f; row[583] = 0.f; }
}

// ---------------------------------------------------------------------------
// Kernel 3: fold BN into W (fp16); channel order: pe 0..191, dp 192..194, pad 0
// ---------------------------------------------------------------------------
__global__ void prep_w(const float* __restrict__ W, const float* __restrict__ gamma,
                       const float* __restrict__ beta, const float* __restrict__ rmean,
                       const float* __restrict__ rvar) {
    int t = blockIdx.x * blockDim.x + threadIdx.x;
    if (t < Cv) {
        float inv = gamma[t] * rsqrtf(rvar[t] + 1e-5f);
        g_bias[t] = beta[t] - rmean[t] * inv;
    }
    if (t >= 192 * (WSTRIDE / 2)) return;
    int o = t / (WSTRIDE / 2), c = t % (WSTRIDE / 2);
    float w = 0.f;
    if (c < CIN) {
        int cold = (c < Cv) ? (c + 3) : (c - Cv);
        w = W[o * CIN + cold] * gamma[o] * rsqrtf(rvar[o] + 1e-5f);
    }
    g_wh[t] = __float2half_rn(w);
}

// ---------------------------------------------------------------------------
// Kernel 4: persistent main. tile = 64 points (2 n x 32 neighbors).
// 512 threads, warp grid 4(M) x 4(N). Build via contiguous table rows (no scatter).
// ---------------------------------------------------------------------------
__global__ void __launch_bounds__(TPB, 1) local_agg_mma(
    const float* __restrict__ p, const int* __restrict__ idx,
    float* __restrict__ out)
{
    extern __shared__ char sm[];
    const unsigned sb = smem_u32(sm);
    const int t = threadIdx.x;
    const int lane = t & 31, wid = t >> 5;
    const int wm = wid >> 2, wn = wid & 3;

    // load W plane + zero-pad H channels 196..207 (bytes 392..415 per row)
    {
        const uint4* s1 = (const uint4*)g_wh;
        uint4* d1 = (uint4*)(sm + SM_WH);
#pragma unroll 4
        for (int i = t; i < W_BYTES / 16; i += TPB) d1[i] = s1[i];
        if (t < 128) {
            int plane = t >> 6, r = t & 63;
            char* a = sm + (plane ? SM_HL : SM_HH) + r * WSTRIDE + 392;
            *(uint2*)(a) = make_uint2(0u, 0u);
            *(uint2*)(a + 8) = make_uint2(0u, 0u);
            *(uint2*)(a + 16) = make_uint2(0u, 0u);
        }
    }
    __syncthreads();

    const unsigned lrow = (unsigned)(lane & 15) * WSTRIDE + ((unsigned)(lane >> 4) << 4);
    const unsigned hAH = sb + SM_HH + (unsigned)wm * 16 * WSTRIDE + lrow;
    const unsigned hAL = sb + SM_HL + (unsigned)wm * 16 * WSTRIDE + lrow;
    const unsigned bWH = sb + SM_WH + (unsigned)wn * 48 * WSTRIDE + lrow;
    float* stage = (float*)(sm + SM_STAGE);
    float* snc = (float*)(sm + SM_SNC);       // [2][200]: S[96] C[96] pn[3]

    const int pl = t >> 3;                    // point within tile (0..63)
    const int sg = t & 7;                     // channel segment (24 ch each)

#pragma unroll 1
    for (int tile = blockIdx.x; tile < NTILES; tile += GRID_MAIN) {
        const int b0 = tile >> 11;
        const int n0 = (tile * 2) & (Nv - 1);

        // ---- stage center-point S/C/p (coalesced) ----
        if (t < 416) {
            const int nn = t / 208, i = t % 208;
            if (i < 195) {
                const float* rown = g_tab + (size_t)(b0 * Nv + n0 + nn) * ROWF;
                snc[nn * 200 + i] = __ldg(rown + 384 + i);
            }
        }
        __syncthreads();

        // ---- build H hi+lo from table rows (contiguous loads, pure FMA) ----
        {
            const int flat = tile * 64 + pl;
            const int j = __ldg(idx + flat);
            const float* rowj = g_tab + (size_t)(b0 * Nv + j) * ROWF;
            const int nn = pl >> 5;
            const float* S = snc + nn * 200;
            const float* C = S + 96;
            const unsigned hdst = sb + SM_HH + (unsigned)pl * WSTRIDE + (unsigned)sg * 48;
            const unsigned ldst = sb + SM_HL + (unsigned)pl * WSTRIDE + (unsigned)sg * 48;
#pragma unroll
            for (int ch = 0; ch < 6; ch++) {
                const int c = sg * 24 + ch * 4;
                float4 a1 = *(const float4*)(rowj + c);
                float4 a2 = *(const float4*)(rowj + 192 + c);
                const int d = c >> 6, e = c & 63, f0 = e & 31;
                float4 sn = *(const float4*)(S + d * 32 + f0);
                float4 cn = *(const float4*)(C + d * 32 + f0);
                float v0, v1, v2, v3;
                if (e < 32) {      // sin(uj-un)*g
                    v0 = a1.x * cn.x - a2.x * sn.x;
                    v1 = a1.y * cn.y - a2.y * sn.y;
                    v2 = a1.z * cn.z - a2.z * sn.z;
                    v3 = a1.w * cn.w - a2.w * sn.w;
                } else {           // cos(uj-un)*g
                    v0 = a2.x * cn.x + a1.x * sn.x;
                    v1 = a2.y * cn.y + a1.y * sn.y;
                    v2 = a2.z * cn.z + a1.z * sn.z;
                    v3 = a2.w * cn.w + a1.w * sn.w;
                }
                __half2 h0 = __float22half2_rn(make_float2(v0, v1));
                __half2 h1 = __float22half2_rn(make_float2(v2, v3));
                __half2 l0 = __float22half2_rn(make_float2(v0 - __half2float(__low2half(h0)),
                                                           v1 - __half2float(__high2half(h0))));
                __half2 l1 = __float22half2_rn(make_float2(v2 - __half2float(__low2half(h1)),
                                                           v3 - __half2float(__high2half(h1))));
                asm volatile("st.shared.v2.b32 [%0], {%1,%2};"
                    :: "r"(hdst + ch * 8), "r"(*(unsigned*)&h0), "r"(*(unsigned*)&h1));
                asm volatile("st.shared.v2.b32 [%0], {%1,%2};"
                    :: "r"(ldst + ch * 8), "r"(*(unsigned*)&l0), "r"(*(unsigned*)&l1));
            }
            if (sg == 7) {         // dp channels 192..195 (195 = 0)
                float4 pj4 = *(const float4*)(rowj + 576);
                const float* PN = S + 192;
                float v0 = pj4.x - PN[0], v1 = pj4.y - PN[1], v2 = pj4.z - PN[2];
                __half2 h0 = __float22half2_rn(make_float2(v0, v1));
                __half2 h1 = __float22half2_rn(make_float2(v2, 0.f));
                __half2 l0 = __float22half2_rn(make_float2(v0 - __half2float(__low2half(h0)),
                                                           v1 - __half2float(__high2half(h0))));
                __half2 l1 = __float22half2_rn(make_float2(v2 - __half2float(__low2half(h1)), 0.f));
                unsigned hd2 = sb + SM_HH + (unsigned)pl * WSTRIDE + 384;
                unsigned ld2 = sb + SM_HL + (unsigned)pl * WSTRIDE + 384;
                asm volatile("st.shared.v2.b32 [%0], {%1,%2};"
                    :: "r"(hd2), "r"(*(unsigned*)&h0), "r"(*(unsigned*)&h1));
                asm volatile("st.shared.v2.b32 [%0], {%1,%2};"
                    :: "r"(ld2), "r"(*(unsigned*)&l0), "r"(*(unsigned*)&l1));
            }
        }
        __syncthreads();

        // ---- pipelined k-loop: Ah*W + Al*W ----
        float acc[6][4];
#pragma unroll
        for (int i = 0; i < 6; i++)
#pragma unroll
            for (int r = 0; r < 4; r++) acc[i][r] = 0.f;

        unsigned AH[2][4], AL[2][4], WF[2][3][4];
        LDSM4(AH[0], hAH);
        LDSM4(AL[0], hAL);
#pragma unroll
        for (int q = 0; q < 3; q++) LDSM4(WF[0][q], bWH + q * 16 * WSTRIDE);

#pragma unroll
        for (int s = 0; s < NSTEP; s++) {
            const int cur = s & 1, nxt = cur ^ 1;
            if (s + 1 < NSTEP) {
                const unsigned ks = (unsigned)(s + 1) * 32;
                LDSM4(AH[nxt], hAH + ks);
                LDSM4(AL[nxt], hAL + ks);
#pragma unroll
                for (int q = 0; q < 3; q++) LDSM4(WF[nxt][q], bWH + q * 16 * WSTRIDE + ks);
            }
#pragma unroll
            for (int q = 0; q < 3; q++) {
                MMA(acc[2 * q],     AH[cur], WF[cur][q][0], WF[cur][q][2]);
                MMA(acc[2 * q + 1], AH[cur], WF[cur][q][1], WF[cur][q][3]);
                MMA(acc[2 * q],     AL[cur], WF[cur][q][0], WF[cur][q][2]);
                MMA(acc[2 * q + 1], AL[cur], WF[cur][q][1], WF[cur][q][3]);
            }
        }

        // ---- epilogue: max over warp's 16 rows, stage per wm ----
#pragma unroll
        for (int nf = 0; nf < 6; nf++) {
            float v0 = fmaxf(acc[nf][0], acc[nf][2]);
            float v1 = fmaxf(acc[nf][1], acc[nf][3]);
#pragma unroll
            for (int off = 4; off < 32; off <<= 1) {
                v0 = fmaxf(v0, __shfl_xor_sync(0xffffffffu, v0, off));
                v1 = fmaxf(v1, __shfl_xor_sync(0xffffffffu, v1, off));
            }
            if (lane < 4)
                *(float2*)(stage + wm * Cv + wn * 48 + nf * 8 + 2 * lane) = make_float2(v0, v1);
        }
        __syncthreads();

        if (t < Cv) {
            const float bias = __ldg(g_bias + t);
            float2 o2;
            o2.x = fmaxf(fmaxf(stage[0 * Cv + t], stage[1 * Cv + t]) + bias, 0.f);
            o2.y = fmaxf(fmaxf(stage[2 * Cv + t], stage[3 * Cv + t]) + bias, 0.f);
            *(float2*)(out + ((size_t)(b0 * Cv + t)) * Nv + n0) = o2;
        }
        __syncthreads();
    }
}

// ---------------------------------------------------------------------------
extern "C" void kernel_launch(void* const* d_in, const int* in_sizes, int n_in,
                              void* d_out, int out_size) {
    const float* p     = (const float*)d_in[0];
    const float* x     = (const float*)d_in[1];
    const int*   idx   = (const int*)d_in[2];
    const float* W     = (const float*)d_in[3];
    const float* gamma = (const float*)d_in[4];
    const float* beta  = (const float*)d_in[5];
    const float* rmean = (const float*)d_in[6];
    const float* rvar  = (const float*)d_in[7];
    float* out = (float*)d_out;

    cudaFuncSetAttribute(local_agg_mma, cudaFuncAttributeMaxDynamicSharedMemorySize, SMEM_TOTAL);

    dim3 tb(32, 8);
    dim3 tg(Nv / 32, Cv / 32, Bv);
    transpose_add1<<<tg, tb>>>(x);
    table_pre<<<(Bv * Nv * 32 + 255) / 256, 256>>>(p);
    prep_w<<<(192 * (WSTRIDE / 2) + 255) / 256, 256>>>(W, gamma, beta, rmean, rvar);
    local_agg_mma<<<GRID_MAIN, TPB, SMEM_TOTAL>>>(p, idx, out);
}

// round 9
// speedup vs baseline: 4.3505x; 1.1873x over previous
#include <cuda_runtime.h>
#include <cuda_fp16.h>
#include <cstdint>

#define Bv 4
#define Nv 4096
#define Cv 192
#define CIN 195
#define NSTEP 13
#define WSTRIDE 432                   // 108 words = 12 mod 32 -> conflict-free LDSM
#define W_BYTES (192 * WSTRIDE)       // 82944
#define H_BYTES (128 * WSTRIDE)       // 55296
#define SM_WH 0
#define SM_HH W_BYTES
#define SM_HL (W_BYTES + H_BYTES)
#define SM_STAGE (W_BYTES + 2 * H_BYTES)          // 193536
#define SM_SNC (SM_STAGE + 4 * Cv * 4)            // 196608
#define SMEM_TOTAL (SM_SNC + 4 * 200 * 4)         // 199808
#define NTILES (Bv * Nv / 4)          // 4096 tiles of 128 points (4 n each)
#define GRID_MAIN 152
#define TPB 512
#define ROWF 584                      // floats per table row (2336 B)

// ---------------- device scratch ----------------
__device__ float g_xt[Bv * Nv * Cv];              // (x+1), [b][n][c]
__device__ float g_tab[Bv * Nv * ROWF];           // per-point: A1[192] A2[192] S[96] C[96] p[3]
__device__ __half g_wh[192 * (WSTRIDE / 2)];      // fp16 BN-folded W
__device__ float g_bias[Cv];

// ---------------- PTX helpers ----------------
__device__ __forceinline__ unsigned smem_u32(const void* p) {
    unsigned a;
    asm("{ .reg .u64 t; cvta.to.shared.u64 t, %1; cvt.u32.u64 %0, t; }" : "=r"(a) : "l"(p));
    return a;
}
#define LDSM4(r, a) \
    asm volatile("ldmatrix.sync.aligned.m8n8.x4.shared.b16 {%0,%1,%2,%3}, [%4];" \
        : "=r"((r)[0]), "=r"((r)[1]), "=r"((r)[2]), "=r"((r)[3]) : "r"(a))
#define MMA(d, a, b0, b1) \
    asm volatile("mma.sync.aligned.m16n8k16.row.col.f32.f16.f16.f32 " \
        "{%0,%1,%2,%3},{%4,%5,%6,%7},{%8,%9},{%0,%1,%2,%3};" \
        : "+f"((d)[0]), "+f"((d)[1]), "+f"((d)[2]), "+f"((d)[3]) \
        : "r"((a)[0]), "r"((a)[1]), "r"((a)[2]), "r"((a)[3]), "r"(b0), "r"(b1))

// ---------------------------------------------------------------------------
// Kernel 1: transpose x [B,C,N] -> xt [B,N,C], fused +1
// ---------------------------------------------------------------------------
__global__ void transpose_add1(const float* __restrict__ x) {
    __shared__ float tile[32][33];
    int n0 = blockIdx.x * 32, c0 = blockIdx.y * 32, b = blockIdx.z;
    int tx = threadIdx.x, ty = threadIdx.y;
#pragma unroll
    for (int i = 0; i < 4; i++)
        tile[ty + i * 8][tx] = x[((size_t)b * Cv + c0 + ty + i * 8) * Nv + n0 + tx];
    __syncthreads();
#pragma unroll
    for (int i = 0; i < 4; i++)
        g_xt[((size_t)b * Nv + n0 + ty + i * 8) * Cv + c0 + tx] = tile[tx][ty + i * 8] + 1.0f;
}

// ---------------------------------------------------------------------------
// Kernel 2: per-point table
// ---------------------------------------------------------------------------
__global__ void table_pre(const float* __restrict__ p) {
    int t = blockIdx.x * blockDim.x + threadIdx.x;
    if (t >= Bv * Nv * 32) return;
    int f = t & 31, pt = t >> 5;
    float m = (float)exp2(-(double)f * (8.9657842846620870436 / 32.0));
    float* row = g_tab + (size_t)pt * ROWF;
    const float* xr = g_xt + (size_t)pt * Cv;
#pragma unroll
    for (int d = 0; d < 3; d++) {
        float s, c;
        sincosf(50.0f * p[pt * 3 + d] * m, &s, &c);
        int c1 = d * 64 + f, c2 = c1 + 32, i96 = d * 32 + f;
        float g1 = xr[c1], g2 = xr[c2];
        row[c1] = s * g1;        row[c2] = s * g2;        // A1
        row[192 + c1] = c * g1;  row[192 + c2] = c * g2;  // A2
        row[384 + i96] = s;      row[480 + i96] = c;      // raw S, C
    }
    if (f < 3) row[576 + f] = p[pt * 3 + f];
    if (f == 3) { row[579] = 0.f; row[580] = 0.f; row[581] = 0.f; row[582] = 0.f; row[583] = 0.f; }
}

// ---------------------------------------------------------------------------
// Kernel 3: fold BN into W (fp16); channel order: pe 0..191, dp 192..194, pad 0
// ---------------------------------------------------------------------------
__global__ void prep_w(const float* __restrict__ W, const float* __restrict__ gamma,
                       const float* __restrict__ beta, const float* __restrict__ rmean,
                       const float* __restrict__ rvar) {
    int t = blockIdx.x * blockDim.x + threadIdx.x;
    if (t < Cv) {
        float inv = gamma[t] * rsqrtf(rvar[t] + 1e-5f);
        g_bias[t] = beta[t] - rmean[t] * inv;
    }
    if (t >= 192 * (WSTRIDE / 2)) return;
    int o = t / (WSTRIDE / 2), c = t % (WSTRIDE / 2);
    float w = 0.f;
    if (c < CIN) {
        int cold = (c < Cv) ? (c + 3) : (c - Cv);
        w = W[o * CIN + cold] * gamma[o] * rsqrtf(rvar[o] + 1e-5f);
    }
    g_wh[t] = __float2half_rn(w);
}

// ---------------------------------------------------------------------------
// Kernel 4: persistent main. tile = 128 points (4 n x 32 neighbors).
// 512 threads, warp grid 4(M) x 4(N): warp tile 32 rows x 48 cols.
// Build: 4 threads/point, lane-contiguous 64B loads.
// ---------------------------------------------------------------------------
__global__ void __launch_bounds__(TPB, 1) local_agg_mma(
    const float* __restrict__ p, const int* __restrict__ idx,
    float* __restrict__ out)
{
    extern __shared__ char sm[];
    const unsigned sb = smem_u32(sm);
    const int t = threadIdx.x;
    const int lane = t & 31, wid = t >> 5;
    const int wm = wid >> 2, wn = wid & 3;

    // load W plane + zero-pad H channels 196..207 (bytes 392..415) on both planes
    // NOTE: +392 is only 8-byte aligned -> uint2 stores.
    {
        const uint4* s1 = (const uint4*)g_wh;
        uint4* d1 = (uint4*)(sm + SM_WH);
#pragma unroll 4
        for (int i = t; i < W_BYTES / 16; i += TPB) d1[i] = s1[i];
        if (t < 256) {
            int plane = t >> 7, r = t & 127;
            char* a = sm + (plane ? SM_HL : SM_HH) + r * WSTRIDE + 392;
            *(uint2*)(a) = make_uint2(0u, 0u);
            *(uint2*)(a + 8) = make_uint2(0u, 0u);
            *(uint2*)(a + 16) = make_uint2(0u, 0u);
        }
    }
    __syncthreads();

    const unsigned lrow = (unsigned)(lane & 15) * WSTRIDE + ((unsigned)(lane >> 4) << 4);
    const unsigned hAH = sb + SM_HH + (unsigned)wm * 32 * WSTRIDE + lrow;
    const unsigned hAL = sb + SM_HL + (unsigned)wm * 32 * WSTRIDE + lrow;
    const unsigned bWH = sb + SM_WH + (unsigned)wn * 48 * WSTRIDE + lrow;
    float* stage = (float*)(sm + SM_STAGE);
    float* snc = (float*)(sm + SM_SNC);       // [4][200]: S[96] C[96] pn[3]

    const int pl = t >> 2;                    // point within tile (0..127)
    const int sg = t & 3;                     // channel segment

#pragma unroll 1
    for (int tile = blockIdx.x; tile < NTILES; tile += GRID_MAIN) {
        const int b0 = tile >> 10;
        const int n0 = (tile * 4) & (Nv - 1);

        // ---- stage the 4 center points' S/C/p (strided: 832 items, 512 thr) ----
        for (int i = t; i < 4 * 208; i += TPB) {
            const int nn = i / 208, ii = i % 208;
            if (ii < 195) {
                const float* rown = g_tab + (size_t)(b0 * Nv + n0 + nn) * ROWF;
                snc[nn * 200 + ii] = __ldg(rown + 384 + ii);
            }
        }
        __syncthreads();

        // ---- build H hi+lo (contiguous 64B/point loads, pure FMA) ----
        {
            const int flat = tile * 128 + pl;
            const int j = __ldg(idx + flat);
            const float* rowj = g_tab + (size_t)(b0 * Nv + j) * ROWF;
            const int nn = pl >> 5;
            const float* S = snc + nn * 200;
            const float* C = S + 96;
            const unsigned hdst = sb + SM_HH + (unsigned)pl * WSTRIDE + (unsigned)sg * 8;
            const unsigned ldst = sb + SM_HL + (unsigned)pl * WSTRIDE + (unsigned)sg * 8;
#pragma unroll
            for (int ch = 0; ch < 12; ch++) {
                const int c = ch * 16 + sg * 4;      // lanes contiguous: 4 lanes cover 64B
                float4 a1 = *(const float4*)(rowj + c);
                float4 a2 = *(const float4*)(rowj + 192 + c);
                const int d = c >> 6, e = c & 63, f0 = e & 31;
                float4 sn = *(const float4*)(S + d * 32 + f0);
                float4 cn = *(const float4*)(C + d * 32 + f0);
                float v0, v1, v2, v3;
                if (e < 32) {      // sin(uj-un)*g
                    v0 = a1.x * cn.x - a2.x * sn.x;
                    v1 = a1.y * cn.y - a2.y * sn.y;
                    v2 = a1.z * cn.z - a2.z * sn.z;
                    v3 = a1.w * cn.w - a2.w * sn.w;
                } else {           // cos(uj-un)*g
                    v0 = a2.x * cn.x + a1.x * sn.x;
                    v1 = a2.y * cn.y + a1.y * sn.y;
                    v2 = a2.z * cn.z + a1.z * sn.z;
                    v3 = a2.w * cn.w + a1.w * sn.w;
                }
                __half2 h0 = __float22half2_rn(make_float2(v0, v1));
                __half2 h1 = __float22half2_rn(make_float2(v2, v3));
                __half2 l0 = __float22half2_rn(make_float2(v0 - __half2float(__low2half(h0)),
                                                           v1 - __half2float(__high2half(h0))));
                __half2 l1 = __float22half2_rn(make_float2(v2 - __half2float(__low2half(h1)),
                                                           v3 - __half2float(__high2half(h1))));
                asm volatile("st.shared.v2.b32 [%0], {%1,%2};"
                    :: "r"(hdst + ch * 32), "r"(*(unsigned*)&h0), "r"(*(unsigned*)&h1));
                asm volatile("st.shared.v2.b32 [%0], {%1,%2};"
                    :: "r"(ldst + ch * 32), "r"(*(unsigned*)&l0), "r"(*(unsigned*)&l1));
            }
            if (sg == 0) {         // dp channels 192..195(pad)
                float4 pj4 = *(const float4*)(rowj + 576);
                const float* PN = S + 192;
                float v0 = pj4.x - PN[0], v1 = pj4.y - PN[1], v2 = pj4.z - PN[2];
                __half2 h0 = __float22half2_rn(make_float2(v0, v1));
                __half2 h1 = __float22half2_rn(make_float2(v2, 0.f));
                __half2 l0 = __float22half2_rn(make_float2(v0 - __half2float(__low2half(h0)),
                                                           v1 - __half2float(__high2half(h0))));
                __half2 l1 = __float22half2_rn(make_float2(v2 - __half2float(__low2half(h1)), 0.f));
                unsigned hd2 = sb + SM_HH + (unsigned)pl * WSTRIDE + 384;
                unsigned ld2 = sb + SM_HL + (unsigned)pl * WSTRIDE + 384;
                asm volatile("st.shared.v2.b32 [%0], {%1,%2};"
                    :: "r"(hd2), "r"(*(unsigned*)&h0), "r"(*(unsigned*)&h1));
                asm volatile("st.shared.v2.b32 [%0], {%1,%2};"
                    :: "r"(ld2), "r"(*(unsigned*)&l0), "r"(*(unsigned*)&l1));
            }
        }
        __syncthreads();

        // ---- pipelined k-loop: (Ah + Al) x W, W/AH double-buffered, AL in-step ----
        float acc[12][4];
#pragma unroll
        for (int i = 0; i < 12; i++)
#pragma unroll
            for (int r = 0; r < 4; r++) acc[i][r] = 0.f;

        unsigned AH[2][2][4], AL[2][4], WF[2][3][4];
#pragma unroll
        for (int mf = 0; mf < 2; mf++) LDSM4(AH[0][mf], hAH + mf * 16 * WSTRIDE);
#pragma unroll
        for (int q = 0; q < 3; q++) LDSM4(WF[0][q], bWH + q * 16 * WSTRIDE);

#pragma unroll
        for (int s = 0; s < NSTEP; s++) {
            const int cur = s & 1, nxt = cur ^ 1;
            const unsigned ks = (unsigned)s * 32;
            if (s + 1 < NSTEP) {
#pragma unroll
                for (int mf = 0; mf < 2; mf++) LDSM4(AH[nxt][mf], hAH + mf * 16 * WSTRIDE + ks + 32);
#pragma unroll
                for (int q = 0; q < 3; q++) LDSM4(WF[nxt][q], bWH + q * 16 * WSTRIDE + ks + 32);
            }
#pragma unroll
            for (int mf = 0; mf < 2; mf++)
#pragma unroll
                for (int q = 0; q < 3; q++) {
                    MMA(acc[mf * 6 + 2 * q],     AH[cur][mf], WF[cur][q][0], WF[cur][q][2]);
                    MMA(acc[mf * 6 + 2 * q + 1], AH[cur][mf], WF[cur][q][1], WF[cur][q][3]);
                }
#pragma unroll
            for (int mf = 0; mf < 2; mf++) LDSM4(AL[mf], hAL + mf * 16 * WSTRIDE + ks);
#pragma unroll
            for (int mf = 0; mf < 2; mf++)
#pragma unroll
                for (int q = 0; q < 3; q++) {
                    MMA(acc[mf * 6 + 2 * q],     AL[mf], WF[cur][q][0], WF[cur][q][2]);
                    MMA(acc[mf * 6 + 2 * q + 1], AL[mf], WF[cur][q][1], WF[cur][q][3]);
                }
        }

        // ---- epilogue: max over warp's 32 rows (one n), stage ----
#pragma unroll
        for (int nf = 0; nf < 6; nf++) {
            float v0 = fmaxf(fmaxf(acc[nf][0], acc[nf][2]), fmaxf(acc[6 + nf][0], acc[6 + nf][2]));
            float v1 = fmaxf(fmaxf(acc[nf][1], acc[nf][3]), fmaxf(acc[6 + nf][1], acc[6 + nf][3]));
#pragma unroll
            for (int off = 4; off < 32; off <<= 1) {
                v0 = fmaxf(v0, __shfl_xor_sync(0xffffffffu, v0, off));
                v1 = fmaxf(v1, __shfl_xor_sync(0xffffffffu, v1, off));
            }
            if (lane < 4)
                *(float2*)(stage + wm * Cv + wn * 48 + nf * 8 + 2 * lane) = make_float2(v0, v1);
        }
        __syncthreads();

        if (t < Cv) {
            const float bias = __ldg(g_bias + t);
            float4 o4;
            o4.x = fmaxf(stage[0 * Cv + t] + bias, 0.f);
            o4.y = fmaxf(stage[1 * Cv + t] + bias, 0.f);
            o4.z = fmaxf(stage[2 * Cv + t] + bias, 0.f);
            o4.w = fmaxf(stage[3 * Cv + t] + bias, 0.f);
            *(float4*)(out + ((size_t)(b0 * Cv + t)) * Nv + n0) = o4;
        }
        __syncthreads();
    }
}

// ---------------------------------------------------------------------------
extern "C" void kernel_launch(void* const* d_in, const int* in_sizes, int n_in,
                              void* d_out, int out_size) {
    const float* p     = (const float*)d_in[0];
    const float* x     = (const float*)d_in[1];
    const int*   idx   = (const int*)d_in[2];
    const float* W     = (const float*)d_in[3];
    const float* gamma = (const float*)d_in[4];
    const float* beta  = (const float*)d_in[5];
    const float* rmean = (const float*)d_in[6];
    const float* rvar  = (const float*)d_in[7];
    float* out = (float*)d_out;

    cudaFuncSetAttribute(local_agg_mma, cudaFuncAttributeMaxDynamicSharedMemorySize, SMEM_TOTAL);

    dim3 tb(32, 8);
    dim3 tg(Nv / 32, Cv / 32, Bv);
    transpose_add1<<<tg, tb>>>(x);
    table_pre<<<(Bv * Nv * 32 + 255) / 256, 256>>>(p);
    prep_w<<<(192 * (WSTRIDE / 2) + 255) / 256, 256>>>(W, gamma, beta, rmean, rvar);
    local_agg_mma<<<GRID_MAIN, TPB, SMEM_TOTAL>>>(p, idx, out);
}

// round 10
// speedup vs baseline: 4.3531x; 1.0006x over previous
#include <cuda_runtime.h>
#include <cuda_fp16.h>
#include <cstdint>

#define Bv 4
#define Nv 4096
#define Cv 192
#define CIN 195
#define NSTEP 13
#define WSTRIDE 432                   // 108 words = 12 mod 32 -> conflict-free LDSM
#define W_BYTES (192 * WSTRIDE)       // 82944
#define H_BYTES (128 * WSTRIDE)       // 55296
#define SM_WH 0
#define SM_HH W_BYTES
#define SM_HL (W_BYTES + H_BYTES)
#define SM_STAGE (W_BYTES + 2 * H_BYTES)          // 193536
#define SM_SNC (SM_STAGE + 4 * Cv * 4)            // 196608
#define SMEM_TOTAL (SM_SNC + 4 * 200 * 4)         // 199808
#define NTILES (Bv * Nv / 4)          // 4096 tiles of 128 points (4 n each)
#define GRID_MAIN 152
#define TPB 512
#define ROWF 584                      // floats per table row (2336 B)

// ---------------- device scratch ----------------
__device__ float g_xt[Bv * Nv * Cv];              // (x+1), [b][n][c]
__device__ float g_tab[Bv * Nv * ROWF];           // per-point: A1[192] A2[192] S[96] C[96] p[3]
__device__ __half g_wh[192 * (WSTRIDE / 2)];      // fp16 BN-folded W
__device__ float g_bias[Cv];

// ---------------- PTX helpers ----------------
__device__ __forceinline__ unsigned smem_u32(const void* p) {
    unsigned a;
    asm("{ .reg .u64 t; cvta.to.shared.u64 t, %1; cvt.u32.u64 %0, t; }" : "=r"(a) : "l"(p));
    return a;
}
#define LDSM4(r, a) \
    asm volatile("ldmatrix.sync.aligned.m8n8.x4.shared.b16 {%0,%1,%2,%3}, [%4];" \
        : "=r"((r)[0]), "=r"((r)[1]), "=r"((r)[2]), "=r"((r)[3]) : "r"(a))
#define MMA(d, a, b0, b1) \
    asm volatile("mma.sync.aligned.m16n8k16.row.col.f32.f16.f16.f32 " \
        "{%0,%1,%2,%3},{%4,%5,%6,%7},{%8,%9},{%0,%1,%2,%3};" \
        : "+f"((d)[0]), "+f"((d)[1]), "+f"((d)[2]), "+f"((d)[3]) \
        : "r"((a)[0]), "r"((a)[1]), "r"((a)[2]), "r"((a)[3]), "r"(b0), "r"(b1))

// ---------------------------------------------------------------------------
// Kernel 1: transpose x [B,C,N] -> xt [B,N,C], fused +1
// ---------------------------------------------------------------------------
__global__ void transpose_add1(const float* __restrict__ x) {
    __shared__ float tile[32][33];
    int n0 = blockIdx.x * 32, c0 = blockIdx.y * 32, b = blockIdx.z;
    int tx = threadIdx.x, ty = threadIdx.y;
#pragma unroll
    for (int i = 0; i < 4; i++)
        tile[ty + i * 8][tx] = x[((size_t)b * Cv + c0 + ty + i * 8) * Nv + n0 + tx];
    __syncthreads();
#pragma unroll
    for (int i = 0; i < 4; i++)
        g_xt[((size_t)b * Nv + n0 + ty + i * 8) * Cv + c0 + tx] = tile[tx][ty + i * 8] + 1.0f;
}

// ---------------------------------------------------------------------------
// Kernel 2: per-point table
// ---------------------------------------------------------------------------
__global__ void table_pre(const float* __restrict__ p) {
    int t = blockIdx.x * blockDim.x + threadIdx.x;
    if (t >= Bv * Nv * 32) return;
    int f = t & 31, pt = t >> 5;
    float m = (float)exp2(-(double)f * (8.9657842846620870436 / 32.0));
    float* row = g_tab + (size_t)pt * ROWF;
    const float* xr = g_xt + (size_t)pt * Cv;
#pragma unroll
    for (int d = 0; d < 3; d++) {
        float s, c;
        sincosf(50.0f * p[pt * 3 + d] * m, &s, &c);
        int c1 = d * 64 + f, c2 = c1 + 32, i96 = d * 32 + f;
        float g1 = xr[c1], g2 = xr[c2];
        row[c1] = s * g1;        row[c2] = s * g2;        // A1
        row[192 + c1] = c * g1;  row[192 + c2] = c * g2;  // A2
        row[384 + i96] = s;      row[480 + i96] = c;      // raw S, C
    }
    if (f < 3) row[576 + f] = p[pt * 3 + f];
    if (f == 3) { row[579] = 0.f; row[580] = 0.f; row[581] = 0.f; row[582] = 0.f; row[583] = 0.f; }
}

// ---------------------------------------------------------------------------
// Kernel 3: fold BN into W (fp16); channel order: pe 0..191, dp 192..194, pad 0
// ---------------------------------------------------------------------------
__global__ void prep_w(const float* __restrict__ W, const float* __restrict__ gamma,
                       const float* __restrict__ beta, const float* __restrict__ rmean,
                       const float* __restrict__ rvar) {
    int t = blockIdx.x * blockDim.x + threadIdx.x;
    if (t < Cv) {
        float inv = gamma[t] * rsqrtf(rvar[t] + 1e-5f);
        g_bias[t] = beta[t] - rmean[t] * inv;
    }
    if (t >= 192 * (WSTRIDE / 2)) return;
    int o = t / (WSTRIDE / 2), c = t % (WSTRIDE / 2);
    float w = 0.f;
    if (c < CIN) {
        int cold = (c < Cv) ? (c + 3) : (c - Cv);
        w = W[o * CIN + cold] * gamma[o] * rsqrtf(rvar[o] + 1e-5f);
    }
    g_wh[t] = __float2half_rn(w);
}

// ---------------------------------------------------------------------------
// Kernel 4: persistent main. tile = 128 points (4 n x 32 neighbors).
// 512 threads, warp grid 4(M) x 4(N): warp tile 32 rows x 48 cols.
// Build: 4 threads/point, lane-contiguous 64B loads.
// ---------------------------------------------------------------------------
__global__ void __launch_bounds__(TPB, 1) local_agg_mma(
    const float* __restrict__ p, const int* __restrict__ idx,
    float* __restrict__ out)
{
    extern __shared__ char sm[];
    const unsigned sb = smem_u32(sm);
    const int t = threadIdx.x;
    const int lane = t & 31, wid = t >> 5;
    const int wm = wid >> 2, wn = wid & 3;

    // load W plane + zero-pad H channels 196..207 (bytes 392..415) on both planes
    // NOTE: +392 is only 8-byte aligned -> uint2 stores.
    {
        const uint4* s1 = (const uint4*)g_wh;
        uint4* d1 = (uint4*)(sm + SM_WH);
#pragma unroll 4
        for (int i = t; i < W_BYTES / 16; i += TPB) d1[i] = s1[i];
        if (t < 256) {
            int plane = t >> 7, r = t & 127;
            char* a = sm + (plane ? SM_HL : SM_HH) + r * WSTRIDE + 392;
            *(uint2*)(a) = make_uint2(0u, 0u);
            *(uint2*)(a + 8) = make_uint2(0u, 0u);
            *(uint2*)(a + 16) = make_uint2(0u, 0u);
        }
    }
    __syncthreads();

    const unsigned lrow = (unsigned)(lane & 15) * WSTRIDE + ((unsigned)(lane >> 4) << 4);
    const unsigned hAH = sb + SM_HH + (unsigned)wm * 32 * WSTRIDE + lrow;
    const unsigned hAL = sb + SM_HL + (unsigned)wm * 32 * WSTRIDE + lrow;
    const unsigned bWH = sb + SM_WH + (unsigned)wn * 48 * WSTRIDE + lrow;
    float* stage = (float*)(sm + SM_STAGE);
    float* snc = (float*)(sm + SM_SNC);       // [4][200]: S[96] C[96] pn[3]

    const int pl = t >> 2;                    // point within tile (0..127)
    const int sg = t & 3;                     // channel segment

#pragma unroll 1
    for (int tile = blockIdx.x; tile < NTILES; tile += GRID_MAIN) {
        const int b0 = tile >> 10;
        const int n0 = (tile * 4) & (Nv - 1);

        // ---- stage the 4 center points' S/C/p (strided: 832 items, 512 thr) ----
        for (int i = t; i < 4 * 208; i += TPB) {
            const int nn = i / 208, ii = i % 208;
            if (ii < 195) {
                const float* rown = g_tab + (size_t)(b0 * Nv + n0 + nn) * ROWF;
                snc[nn * 200 + ii] = __ldg(rown + 384 + ii);
            }
        }
        __syncthreads();

        // ---- build H hi+lo (contiguous 64B/point loads, pure FMA) ----
        {
            const int flat = tile * 128 + pl;
            const int j = __ldg(idx + flat);
            const float* rowj = g_tab + (size_t)(b0 * Nv + j) * ROWF;
            const int nn = pl >> 5;
            const float* S = snc + nn * 200;
            const float* C = S + 96;
            const unsigned hdst = sb + SM_HH + (unsigned)pl * WSTRIDE + (unsigned)sg * 8;
            const unsigned ldst = sb + SM_HL + (unsigned)pl * WSTRIDE + (unsigned)sg * 8;
#pragma unroll
            for (int ch = 0; ch < 12; ch++) {
                const int c = ch * 16 + sg * 4;      // lanes contiguous: 4 lanes cover 64B
                float4 a1 = *(const float4*)(rowj + c);
                float4 a2 = *(const float4*)(rowj + 192 + c);
                const int d = c >> 6, e = c & 63, f0 = e & 31;
                float4 sn = *(const float4*)(S + d * 32 + f0);
                float4 cn = *(const float4*)(C + d * 32 + f0);
                float v0, v1, v2, v3;
                if (e < 32) {      // sin(uj-un)*g
                    v0 = a1.x * cn.x - a2.x * sn.x;
                    v1 = a1.y * cn.y - a2.y * sn.y;
                    v2 = a1.z * cn.z - a2.z * sn.z;
                    v3 = a1.w * cn.w - a2.w * sn.w;
                } else {           // cos(uj-un)*g
                    v0 = a2.x * cn.x + a1.x * sn.x;
                    v1 = a2.y * cn.y + a1.y * sn.y;
                    v2 = a2.z * cn.z + a1.z * sn.z;
                    v3 = a2.w * cn.w + a1.w * sn.w;
                }
                __half2 h0 = __float22half2_rn(make_float2(v0, v1));
                __half2 h1 = __float22half2_rn(make_float2(v2, v3));
                __half2 l0 = __float22half2_rn(make_float2(v0 - __half2float(__low2half(h0)),
                                                           v1 - __half2float(__high2half(h0))));
                __half2 l1 = __float22half2_rn(make_float2(v2 - __half2float(__low2half(h1)),
                                                           v3 - __half2float(__high2half(h1))));
                asm volatile("st.shared.v2.b32 [%0], {%1,%2};"
                    :: "r"(hdst + ch * 32), "r"(*(unsigned*)&h0), "r"(*(unsigned*)&h1));
                asm volatile("st.shared.v2.b32 [%0], {%1,%2};"
                    :: "r"(ldst + ch * 32), "r"(*(unsigned*)&l0), "r"(*(unsigned*)&l1));
            }
            if (sg == 0) {         // dp channels 192..195(pad)
                float4 pj4 = *(const float4*)(rowj + 576);
                const float* PN = S + 192;
                float v0 = pj4.x - PN[0], v1 = pj4.y - PN[1], v2 = pj4.z - PN[2];
                __half2 h0 = __float22half2_rn(make_float2(v0, v1));
                __half2 h1 = __float22half2_rn(make_float2(v2, 0.f));
                __half2 l0 = __float22half2_rn(make_float2(v0 - __half2float(__low2half(h0)),
                                                           v1 - __half2float(__high2half(h0))));
                __half2 l1 = __float22half2_rn(make_float2(v2 - __half2float(__low2half(h1)), 0.f));
                unsigned hd2 = sb + SM_HH + (unsigned)pl * WSTRIDE + 384;
                unsigned ld2 = sb + SM_HL + (unsigned)pl * WSTRIDE + 384;
                asm volatile("st.shared.v2.b32 [%0], {%1,%2};"
                    :: "r"(hd2), "r"(*(unsigned*)&h0), "r"(*(unsigned*)&h1));
                asm volatile("st.shared.v2.b32 [%0], {%1,%2};"
                    :: "r"(ld2), "r"(*(unsigned*)&l0), "r"(*(unsigned*)&l1));
            }
        }
        __syncthreads();

        // ---- pipelined k-loop: (Ah + Al) x W, W/AH double-buffered, AL in-step ----
        float acc[12][4];
#pragma unroll
        for (int i = 0; i < 12; i++)
#pragma unroll
            for (int r = 0; r < 4; r++) acc[i][r] = 0.f;

        unsigned AH[2][2][4], AL[2][4], WF[2][3][4];
#pragma unroll
        for (int mf = 0; mf < 2; mf++) LDSM4(AH[0][mf], hAH + mf * 16 * WSTRIDE);
#pragma unroll
        for (int q = 0; q < 3; q++) LDSM4(WF[0][q], bWH + q * 16 * WSTRIDE);

#pragma unroll
        for (int s = 0; s < NSTEP; s++) {
            const int cur = s & 1, nxt = cur ^ 1;
            const unsigned ks = (unsigned)s * 32;
            if (s + 1 < NSTEP) {
#pragma unroll
                for (int mf = 0; mf < 2; mf++) LDSM4(AH[nxt][mf], hAH + mf * 16 * WSTRIDE + ks + 32);
#pragma unroll
                for (int q = 0; q < 3; q++) LDSM4(WF[nxt][q], bWH + q * 16 * WSTRIDE + ks + 32);
            }
#pragma unroll
            for (int mf = 0; mf < 2; mf++)
#pragma unroll
                for (int q = 0; q < 3; q++) {
                    MMA(acc[mf * 6 + 2 * q],     AH[cur][mf], WF[cur][q][0], WF[cur][q][2]);
                    MMA(acc[mf * 6 + 2 * q + 1], AH[cur][mf], WF[cur][q][1], WF[cur][q][3]);
                }
#pragma unroll
            for (int mf = 0; mf < 2; mf++) LDSM4(AL[mf], hAL + mf * 16 * WSTRIDE + ks);
#pragma unroll
            for (int mf = 0; mf < 2; mf++)
#pragma unroll
                for (int q = 0; q < 3; q++) {
                    MMA(acc[mf * 6 + 2 * q],     AL[mf], WF[cur][q][0], WF[cur][q][2]);
                    MMA(acc[mf * 6 + 2 * q + 1], AL[mf], WF[cur][q][1], WF[cur][q][3]);
                }
        }

        // ---- epilogue: max over warp's 32 rows (one n), stage ----
#pragma unroll
        for (int nf = 0; nf < 6; nf++) {
            float v0 = fmaxf(fmaxf(acc[nf][0], acc[nf][2]), fmaxf(acc[6 + nf][0], acc[6 + nf][2]));
            float v1 = fmaxf(fmaxf(acc[nf][1], acc[nf][3]), fmaxf(acc[6 + nf][1], acc[6 + nf][3]));
#pragma unroll
            for (int off = 4; off < 32; off <<= 1) {
                v0 = fmaxf(v0, __shfl_xor_sync(0xffffffffu, v0, off));
                v1 = fmaxf(v1, __shfl_xor_sync(0xffffffffu, v1, off));
            }
            if (lane < 4)
                *(float2*)(stage + wm * Cv + wn * 48 + nf * 8 + 2 * lane) = make_float2(v0, v1);
        }
        __syncthreads();

        if (t < Cv) {
            const float bias = __ldg(g_bias + t);
            float4 o4;
            o4.x = fmaxf(stage[0 * Cv + t] + bias, 0.f);
            o4.y = fmaxf(stage[1 * Cv + t] + bias, 0.f);
            o4.z = fmaxf(stage[2 * Cv + t] + bias, 0.f);
            o4.w = fmaxf(stage[3 * Cv + t] + bias, 0.f);
            *(float4*)(out + ((size_t)(b0 * Cv + t)) * Nv + n0) = o4;
        }
        __syncthreads();
    }
}

// ---------------------------------------------------------------------------
extern "C" void kernel_launch(void* const* d_in, const int* in_sizes, int n_in,
                              void* d_out, int out_size) {
    const float* p     = (const float*)d_in[0];
    const float* x     = (const float*)d_in[1];
    const int*   idx   = (const int*)d_in[2];
    const float* W     = (const float*)d_in[3];
    const float* gamma = (const float*)d_in[4];
    const float* beta  = (const float*)d_in[5];
    const float* rmean = (const float*)d_in[6];
    const float* rvar  = (const float*)d_in[7];
    float* out = (float*)d_out;

    cudaFuncSetAttribute(local_agg_mma, cudaFuncAttributeMaxDynamicSharedMemorySize, SMEM_TOTAL);

    dim3 tb(32, 8);
    dim3 tg(Nv / 32, Cv / 32, Bv);
    transpose_add1<<<tg, tb>>>(x);
    table_pre<<<(Bv * Nv * 32 + 255) / 256, 256>>>(p);
    prep_w<<<(192 * (WSTRIDE / 2) + 255) / 256, 256>>>(W, gamma, beta, rmean, rvar);
    local_agg_mma<<<GRID_MAIN, TPB, SMEM_TOTAL>>>(p, idx, out);
}